// round 9
// baseline (speedup 1.0000x reference)
#include <cuda_runtime.h>
#include <math.h>

#define BB 32
#define CC 64
#define LL 512
#define VV 8192
#define NTOK_MAX (BB*LL)      /* 16384 */
#define NELEM (BB*CC*LL)      /* 1048576 */
#define TOKB 512              /* tokens per argmax x-block (1/thread) */
#define TR 128                /* codebook rows staged per tile */

// packed f32x2 helpers (sm_100+): lanewise IEEE fma on two packed floats
#define FMA_F32X2(d, a, b, c) \
    asm("fma.rn.f32x2 %0, %1, %2, %3;" : "=l"(d) : "l"(a), "l"(b), "l"(c))
#define UNPACK_F32X2(lo, hi, in) \
    asm("mov.b64 {%0, %1}, %2;" : "=r"(lo), "=r"(hi) : "l"(in))

// ---------------- device scratch (no malloc allowed) ----------------
__device__ float g_cbn[VV*CC];            // normalized codebook, 2MB
__device__ float g_frest[NELEM];          // residual, 4MB
__device__ float g_fhat[NELEM];           // reconstruction, 4MB
__device__ float g_rest_tok[NTOK_MAX*CC]; // downsampled+normalized tokens
__device__ int   g_idx[NTOK_MAX];         // selected codes
__device__ float g_pval[NTOK_MAX*64];     // per-vocab-split partial best val
__device__ int   g_pidx[NTOK_MAX*64];     // per-vocab-split partial best idx
__device__ float g_loss;                  // sum of squared err accum

// ---------------- codebook row-normalize (IEEE sqrt/div, fast-math-proof) ----
__global__ void normalize_cb_kernel(const float* __restrict__ ew) {
    int row = blockIdx.x;
    int lane = threadIdx.x;                 // 32 threads, 2 floats each
    float2 v = reinterpret_cast<const float2*>(ew + row*CC)[lane];
    float ss = v.x*v.x + v.y*v.y;
    #pragma unroll
    for (int off = 16; off > 0; off >>= 1)
        ss += __shfl_xor_sync(0xffffffffu, ss, off);
    float den = fmaxf(__fsqrt_rn(ss), 1e-12f);
    float2 o;
    o.x = __fdiv_rn(v.x, den);
    o.y = __fdiv_rn(v.y, den);
    reinterpret_cast<float2*>(g_cbn + row*CC)[lane] = o;
}

// ---------------- init residual / fhat / loss ----------------
__global__ void init_kernel(const float* __restrict__ f) {
    int i = blockIdx.x*256 + threadIdx.x;
    if (i < NELEM) { g_frest[i] = f[i]; g_fhat[i] = 0.f; }
    if (i == 0) g_loss = 0.f;
}

// ---------- fused area-downsample + row-normalize: warp per token ----------
__global__ void ds_norm_kernel(int s, int r, int ntok) {
    int t = blockIdx.x*8 + (threadIdx.x >> 5);
    if (t >= ntok) return;
    int lane = threadIdx.x & 31;
    int b = t / s, p = t - b*s;
    const float* s0 = g_frest + (b*CC + 2*lane)*LL + p*r;
    const float* s1 = s0 + LL;
    float va = 0.f, vb = 0.f;
    for (int j = 0; j < r; ++j) va += s0[j];
    for (int j = 0; j < r; ++j) vb += s1[j];
    float inv = 1.0f / (float)r;            // r power of two -> exact
    va *= inv; vb *= inv;
    float ss = va*va + vb*vb;
    #pragma unroll
    for (int off = 16; off > 0; off >>= 1)
        ss += __shfl_xor_sync(0xffffffffu, ss, off);
    float den = fmaxf(__fsqrt_rn(ss), 1e-12f);
    float2 o;
    o.x = __fdiv_rn(va, den);
    o.y = __fdiv_rn(vb, den);
    reinterpret_cast<float2*>(g_rest_tok)[t*32 + lane] = o;
}

// ------------- cosine argmax: token-in-registers, codebook broadcast -------
// 512 threads, 1 token per thread (64 regs, loaded ONCE). Codebook rows
// streamed from a 128-row smem tile as pure broadcast LDS.128 (1 LDS per
// 2 FFMA2 -> FMA-bound). Per-token argmax completes thread-locally: no
// reductions, no token smem. Chains a01/a23 over j and (ax+ay)+(az+aw)
// horizontal: bit-identical to all validated rounds; rows scanned in
// ascending v with '>' -> lowest-index tie.
__global__ void __launch_bounds__(512) argmax_kernel(int ntok, int chunk, int vs) {
    __shared__ __align__(16) float4 s_cb[TR*16];   // 32KB tile

    int tid = threadIdx.x;
    int tg  = blockIdx.x * TOKB + tid;
    int tcl = (tg < ntok) ? tg : (ntok - 1);       // clamp for safe load

    // token -> 32 packed-pair registers (64 regs), once per kernel
    unsigned long long tok[32];
    {
        const ulonglong2* p =
            reinterpret_cast<const ulonglong2*>(g_rest_tok + tcl*CC);
        #pragma unroll
        for (int j = 0; j < 16; ++j) {
            ulonglong2 u = p[j];
            tok[2*j]   = u.x;
            tok[2*j+1] = u.y;
        }
    }

    float best = -1e30f; int bidx = 0;
    int vstart = blockIdx.y * chunk;
    int ntiles = chunk / TR;

    for (int tile = 0; tile < ntiles; ++tile) {
        __syncthreads();
        const float4* src = reinterpret_cast<const float4*>(g_cbn)
                          + (size_t)(vstart + tile*TR) * 16;
        #pragma unroll
        for (int k = 0; k < (TR*16)/512; ++k)
            s_cb[tid + k*512] = src[tid + k*512];
        __syncthreads();

        const ulonglong2* cb = reinterpret_cast<const ulonglong2*>(s_cb);
        int vbase = vstart + tile*TR;
        #pragma unroll 2
        for (int row = 0; row < TR; ++row) {
            unsigned long long a01 = 0ull, a23 = 0ull;   // (ax,ay),(az,aw)
            #pragma unroll
            for (int j = 0; j < 16; ++j) {
                ulonglong2 cv = cb[row*16 + j];          // warp broadcast
                FMA_F32X2(a01, cv.x, tok[2*j],   a01);
                FMA_F32X2(a23, cv.y, tok[2*j+1], a23);
            }
            unsigned int uax, uay, uaz, uaw;
            UNPACK_F32X2(uax, uay, a01);
            UNPACK_F32X2(uaz, uaw, a23);
            float d = (__uint_as_float(uax) + __uint_as_float(uay))
                    + (__uint_as_float(uaz) + __uint_as_float(uaw));
            if (d > best) { best = d; bidx = vbase + row; }
        }
    }

    if (tg < ntok) {
        if (vs == 1) g_idx[tg] = bidx;
        else { g_pval[tg*64 + blockIdx.y] = best; g_pidx[tg*64 + blockIdx.y] = bidx; }
    }
}

// ---------------- reduce vocab splits per token (vs>1 only) ----------------
__global__ void reduce_kernel(int ntok, int vs) {
    int t = blockIdx.x*256 + threadIdx.x;
    if (t >= ntok) return;
    float bv = g_pval[t*64]; int bi = g_pidx[t*64];
    for (int sp = 1; sp < vs; ++sp) {
        float ov = g_pval[t*64 + sp]; int oi = g_pidx[t*64 + sp];
        if (ov > bv || (ov == bv && oi < bi)) { bv = ov; bi = oi; }
    }
    g_idx[t] = bi;
}

// ---------------- fused gather + upsample + Phi conv + residual update + loss ----------------
#define TL 64
#define PHI_SMEM_FLOATS (CC*(TL+2) + CC*193 + CC)
__global__ void __launch_bounds__(256) phi_update_kernel(
    const float* __restrict__ f, const float* __restrict__ ew,
    const float* __restrict__ phiw, const float* __restrict__ phib,
    int s, int pidx, float* __restrict__ outp)
{
    extern __shared__ float sm[];
    float* tile = sm;                 // [64][66]
    float* ws   = sm + CC*(TL+2);     // [64][193]
    float* bs   = ws + CC*193;        // [64]

    int b  = blockIdx.x >> 3;
    int l0 = (blockIdx.x & 7) * TL;
    int tid = threadIdx.x;

    const float* wsrc = phiw + pidx*CC*CC*3;
    for (int i = tid; i < CC*192; i += 256) {
        int co = i / 192, rem = i - co*192;
        ws[co*193 + rem] = wsrc[i];
    }
    if (tid < CC) bs[tid] = phib[pidx*CC + tid];

    for (int i = tid; i < CC*(TL+2); i += 256) {
        int ci = i / (TL+2), j = i - ci*(TL+2);
        int l = l0 + j - 1;
        float v = 0.f;
        if (l >= 0 && l < LL) {
            int tokp = (l * s) >> 9;
            int code = g_idx[b*s + tokp];
            v = ew[code*CC + ci];
        }
        tile[ci*(TL+2) + j] = v;
    }
    __syncthreads();

    int co = tid & 63;
    int pbase = (tid >> 6) * 16;
    float acc[16];
    #pragma unroll
    for (int p = 0; p < 16; ++p) acc[p] = 0.f;

    for (int ci = 0; ci < CC; ++ci) {
        const float* wr = ws + co*193 + ci*3;
        float w0 = wr[0], w1 = wr[1], w2 = wr[2];
        const float* hr = tile + ci*(TL+2) + pbase;
        float h[18];
        #pragma unroll
        for (int j = 0; j < 18; ++j) h[j] = hr[j];
        #pragma unroll
        for (int p = 0; p < 16; ++p)
            acc[p] = fmaf(w0, h[p], fmaf(w1, h[p+1], fmaf(w2, h[p+2], acc[p])));
    }

    float ss = 0.f;
    float bb = bs[co];
    #pragma unroll
    for (int p = 0; p < 16; ++p) {
        int l = l0 + pbase + p;
        float hc = tile[co*(TL+2) + pbase + p + 1];
        float y = 0.5f*hc + 0.5f*(acc[p] + bb);
        int gi = (b*CC + co)*LL + l;
        float fh = g_fhat[gi] + y;
        if (outp) {
            outp[gi] = fh;                 // last scale: write output directly
        } else {
            g_fhat[gi] = fh;
            g_frest[gi] -= y;
        }
        float d = fh - f[gi];
        ss = fmaf(d, d, ss);
    }

    #pragma unroll
    for (int off = 16; off > 0; off >>= 1)
        ss += __shfl_xor_sync(0xffffffffu, ss, off);
    __shared__ float red[8];
    int lane = tid & 31, warp = tid >> 5;
    if (lane == 0) red[warp] = ss;
    __syncthreads();
    if (tid == 0) {
        float tot = 0.f;
        #pragma unroll
        for (int w = 0; w < 8; ++w) tot += red[w];
        atomicAdd(&g_loss, tot);
    }
}

// ---------------- tail: loss scalar (+ zero any padding) ----------------
__global__ void loss_kernel(float* __restrict__ out, int out_size) {
    int i = NELEM + blockIdx.x*256 + threadIdx.x;
    if (i >= out_size) return;
    out[i] = (i == NELEM) ? g_loss * (1.25f / (10.0f * (float)NELEM)) : 0.f;
}

// ---------------- launch ----------------
extern "C" void kernel_launch(void* const* d_in, const int* in_sizes, int n_in,
                              void* d_out, int out_size) {
    // Bind inputs BY ELEMENT COUNT (pairwise distinct -> ordering-immune)
    const float* f    = nullptr;
    const float* ew   = nullptr;
    const float* phiw = nullptr;
    const float* phib = nullptr;
    for (int i = 0; i < n_in; ++i) {
        switch (in_sizes[i]) {
            case 1048576: f    = (const float*)d_in[i]; break;
            case 524288:  ew   = (const float*)d_in[i]; break;
            case 49152:   phiw = (const float*)d_in[i]; break;
            case 256:     phib = (const float*)d_in[i]; break;
            default: break;
        }
    }
    float* out = (float*)d_out;

    const int seg[10] = {1,2,4,8,16,32,64,128,256,512};

    // pmap: bit-exact float64 replication of np.linspace + np.argmin(first-wins)
    int pmap[10];
    {
        double start = 1.0 / 12.0;
        double stop  = 1.0 - 1.0 / 12.0;
        double delta = stop - start;
        double step  = delta / 3.0;
        double ticks[4];
        for (int i = 0; i < 4; ++i) ticks[i] = (double)i * step + start;
        ticks[3] = stop;
        for (int si = 0; si < 10; ++si) {
            double x = (double)si / 9.0;
            int best = 0;
            double bd = fabs(ticks[0] - x);
            for (int i = 1; i < 4; ++i) {
                double d = fabs(ticks[i] - x);
                if (d < bd) { bd = d; best = i; }
            }
            pmap[si] = best;
        }
    }

    cudaFuncSetAttribute(phi_update_kernel,
                         cudaFuncAttributeMaxDynamicSharedMemorySize,
                         PHI_SMEM_FLOATS * (int)sizeof(float));

    normalize_cb_kernel<<<VV, 32>>>(ew);
    init_kernel<<<(NELEM + 255)/256, 256>>>(f);

    for (int si = 0; si < 10; ++si) {
        int s = seg[si];
        int ntok = BB * s;
        int r = LL / s;

        ds_norm_kernel<<<(ntok + 7)/8, 256>>>(s, r, ntok);

        int xblocks = (ntok + TOKB - 1)/TOKB;
        int vs = 1;
        while (xblocks * vs < 128 && vs < 64) vs <<= 1;   // pow2; chunk multiple of 128
        int chunk = VV / vs;
        dim3 agrid(xblocks, vs);
        argmax_kernel<<<agrid, 512>>>(ntok, chunk, vs);

        if (vs > 1)
            reduce_kernel<<<(ntok + 255)/256, 256>>>(ntok, vs);

        phi_update_kernel<<<BB*8, 256, PHI_SMEM_FLOATS*(int)sizeof(float)>>>(
            f, ew, phiw, phib, s, pmap[si], (si == 9) ? out : nullptr);
    }

    loss_kernel<<<(out_size - NELEM + 255)/256, 256>>>(out, out_size);
}

// round 10
// speedup vs baseline: 1.6077x; 1.6077x over previous
#include <cuda_runtime.h>
#include <math.h>

#define BB 32
#define CC 64
#define LL 512
#define VV 8192
#define NTOK_MAX (BB*LL)      /* 16384 */
#define NELEM (BB*CC*LL)      /* 1048576 */
#define TOKB 256              /* tokens per argmax x-block (1/thread) */
#define TR 128                /* codebook rows staged per tile */

// packed f32x2 helpers (sm_100+): lanewise IEEE fma on two packed floats
#define FMA_F32X2(d, a, b, c) \
    asm("fma.rn.f32x2 %0, %1, %2, %3;" : "=l"(d) : "l"(a), "l"(b), "l"(c))
#define UNPACK_F32X2(lo, hi, in) \
    asm("mov.b64 {%0, %1}, %2;" : "=r"(lo), "=r"(hi) : "l"(in))

// ---------------- device scratch (no malloc allowed) ----------------
__device__ float g_cbn[VV*CC];            // normalized codebook, 2MB
__device__ float g_frest[NELEM];          // residual, 4MB
__device__ float g_fhat[NELEM];           // reconstruction, 4MB
__device__ float g_rest_tok[NTOK_MAX*CC]; // downsampled+normalized tokens
__device__ int   g_idx[NTOK_MAX];         // selected codes
__device__ float g_pval[NTOK_MAX*64];     // per-vocab-split partial best val
__device__ int   g_pidx[NTOK_MAX*64];     // per-vocab-split partial best idx
__device__ float g_loss;                  // sum of squared err accum

// ---------------- codebook row-normalize (IEEE sqrt/div, fast-math-proof) ----
__global__ void normalize_cb_kernel(const float* __restrict__ ew) {
    int row = blockIdx.x;
    int lane = threadIdx.x;                 // 32 threads, 2 floats each
    float2 v = reinterpret_cast<const float2*>(ew + row*CC)[lane];
    float ss = v.x*v.x + v.y*v.y;
    #pragma unroll
    for (int off = 16; off > 0; off >>= 1)
        ss += __shfl_xor_sync(0xffffffffu, ss, off);
    float den = fmaxf(__fsqrt_rn(ss), 1e-12f);
    float2 o;
    o.x = __fdiv_rn(v.x, den);
    o.y = __fdiv_rn(v.y, den);
    reinterpret_cast<float2*>(g_cbn + row*CC)[lane] = o;
}

// ---------------- init residual / fhat / loss ----------------
__global__ void init_kernel(const float* __restrict__ f) {
    int i = blockIdx.x*256 + threadIdx.x;
    if (i < NELEM) { g_frest[i] = f[i]; g_fhat[i] = 0.f; }
    if (i == 0) g_loss = 0.f;
}

// ---------- fused area-downsample + row-normalize: warp per token ----------
__global__ void ds_norm_kernel(int s, int r, int ntok) {
    int t = blockIdx.x*8 + (threadIdx.x >> 5);
    if (t >= ntok) return;
    int lane = threadIdx.x & 31;
    int b = t / s, p = t - b*s;
    const float* s0 = g_frest + (b*CC + 2*lane)*LL + p*r;
    const float* s1 = s0 + LL;
    float va = 0.f, vb = 0.f;
    for (int j = 0; j < r; ++j) va += s0[j];
    for (int j = 0; j < r; ++j) vb += s1[j];
    float inv = 1.0f / (float)r;            // r power of two -> exact
    va *= inv; vb *= inv;
    float ss = va*va + vb*vb;
    #pragma unroll
    for (int off = 16; off > 0; off >>= 1)
        ss += __shfl_xor_sync(0xffffffffu, ss, off);
    float den = fmaxf(__fsqrt_rn(ss), 1e-12f);
    float2 o;
    o.x = __fdiv_rn(va, den);
    o.y = __fdiv_rn(vb, den);
    reinterpret_cast<float2*>(g_rest_tok)[t*32 + lane] = o;
}

// ------------- cosine argmax: token-in-regs + pipelined row stream ---------
// 256 threads, 1 token/thread (64 regs, loaded once). Codebook rows streamed
// from smem via broadcast LDS.128 into TWO alternating register buffers:
// prefetch row k+1 while computing row k -> LDS latency off the critical
// path; fma-pipe-bound. Chains a01/a23 over j and (ax+ay)+(az+aw) horizontal:
// bit-identical to all validated rounds; rows ascending with '>'.
__global__ void __launch_bounds__(256) argmax_kernel(int ntok, int chunk, int vs) {
    __shared__ __align__(16) float4 s_cb[TR*16];   // 32KB tile

    int tid = threadIdx.x;
    int tg  = blockIdx.x * TOKB + tid;
    int tcl = (tg < ntok) ? tg : (ntok - 1);       // clamp for safe load

    // token -> 32 packed regs (64 f32), once per kernel
    unsigned long long tok[32];
    {
        const ulonglong2* p =
            reinterpret_cast<const ulonglong2*>(g_rest_tok + tcl*CC);
        #pragma unroll
        for (int j = 0; j < 16; ++j) {
            ulonglong2 u = p[j];
            tok[2*j]   = u.x;
            tok[2*j+1] = u.y;
        }
    }

    float best = -1e30f; int bidx = 0;
    int vstart = blockIdx.y * chunk;
    int ntiles = chunk / TR;

    for (int tile = 0; tile < ntiles; ++tile) {
        __syncthreads();
        const float4* src = reinterpret_cast<const float4*>(g_cbn)
                          + (size_t)(vstart + tile*TR) * 16;
        #pragma unroll
        for (int k = 0; k < (TR*16)/256; ++k)      // 8 coalesced float4 stores
            s_cb[tid + k*256] = src[tid + k*256];
        __syncthreads();

        const ulonglong2* cb = reinterpret_cast<const ulonglong2*>(s_cb);
        int vbase = vstart + tile*TR;

        ulonglong2 cur[16], nxt[16];
        #pragma unroll
        for (int j = 0; j < 16; ++j) cur[j] = cb[j];            // row 0

        #pragma unroll 1
        for (int row = 0; row < TR; row += 2) {
            // prefetch row+1 into nxt while computing cur (row)
            #pragma unroll
            for (int j = 0; j < 16; ++j) nxt[j] = cb[(row+1)*16 + j];
            {
                unsigned long long a01 = 0ull, a23 = 0ull;
                #pragma unroll
                for (int j = 0; j < 16; ++j) {
                    FMA_F32X2(a01, cur[j].x, tok[2*j],   a01);
                    FMA_F32X2(a23, cur[j].y, tok[2*j+1], a23);
                }
                unsigned int uax, uay, uaz, uaw;
                UNPACK_F32X2(uax, uay, a01);
                UNPACK_F32X2(uaz, uaw, a23);
                float d = (__uint_as_float(uax) + __uint_as_float(uay))
                        + (__uint_as_float(uaz) + __uint_as_float(uaw));
                if (d > best) { best = d; bidx = vbase + row; }
            }
            // prefetch row+2 into cur while computing nxt (row+1)
            if (row + 2 < TR) {
                #pragma unroll
                for (int j = 0; j < 16; ++j) cur[j] = cb[(row+2)*16 + j];
            }
            {
                unsigned long long a01 = 0ull, a23 = 0ull;
                #pragma unroll
                for (int j = 0; j < 16; ++j) {
                    FMA_F32X2(a01, nxt[j].x, tok[2*j],   a01);
                    FMA_F32X2(a23, nxt[j].y, tok[2*j+1], a23);
                }
                unsigned int uax, uay, uaz, uaw;
                UNPACK_F32X2(uax, uay, a01);
                UNPACK_F32X2(uaz, uaw, a23);
                float d = (__uint_as_float(uax) + __uint_as_float(uay))
                        + (__uint_as_float(uaz) + __uint_as_float(uaw));
                if (d > best) { best = d; bidx = vbase + row + 1; }
            }
        }
    }

    if (tg < ntok) {
        if (vs == 1) g_idx[tg] = bidx;
        else { g_pval[tg*64 + blockIdx.y] = best; g_pidx[tg*64 + blockIdx.y] = bidx; }
    }
}

// ---------------- reduce vocab splits per token (vs>1 only) ----------------
__global__ void reduce_kernel(int ntok, int vs) {
    int t = blockIdx.x*256 + threadIdx.x;
    if (t >= ntok) return;
    float bv = g_pval[t*64]; int bi = g_pidx[t*64];
    for (int sp = 1; sp < vs; ++sp) {
        float ov = g_pval[t*64 + sp]; int oi = g_pidx[t*64 + sp];
        if (ov > bv || (ov == bv && oi < bi)) { bv = ov; bi = oi; }
    }
    g_idx[t] = bi;
}

// ---------------- fused gather + upsample + Phi conv + residual update + loss ----------------
#define TL 64
#define PHI_SMEM_FLOATS (CC*(TL+2) + CC*193 + CC)
__global__ void __launch_bounds__(256) phi_update_kernel(
    const float* __restrict__ f, const float* __restrict__ ew,
    const float* __restrict__ phiw, const float* __restrict__ phib,
    int s, int pidx, float* __restrict__ outp)
{
    extern __shared__ float sm[];
    float* tile = sm;                 // [64][66]
    float* ws   = sm + CC*(TL+2);     // [64][193]
    float* bs   = ws + CC*193;        // [64]

    int b  = blockIdx.x >> 3;
    int l0 = (blockIdx.x & 7) * TL;
    int tid = threadIdx.x;

    const float* wsrc = phiw + pidx*CC*CC*3;
    for (int i = tid; i < CC*192; i += 256) {
        int co = i / 192, rem = i - co*192;
        ws[co*193 + rem] = wsrc[i];
    }
    if (tid < CC) bs[tid] = phib[pidx*CC + tid];

    for (int i = tid; i < CC*(TL+2); i += 256) {
        int ci = i / (TL+2), j = i - ci*(TL+2);
        int l = l0 + j - 1;
        float v = 0.f;
        if (l >= 0 && l < LL) {
            int tokp = (l * s) >> 9;
            int code = g_idx[b*s + tokp];
            v = ew[code*CC + ci];
        }
        tile[ci*(TL+2) + j] = v;
    }
    __syncthreads();

    int co = tid & 63;
    int pbase = (tid >> 6) * 16;
    float acc[16];
    #pragma unroll
    for (int p = 0; p < 16; ++p) acc[p] = 0.f;

    for (int ci = 0; ci < CC; ++ci) {
        const float* wr = ws + co*193 + ci*3;
        float w0 = wr[0], w1 = wr[1], w2 = wr[2];
        const float* hr = tile + ci*(TL+2) + pbase;
        float h[18];
        #pragma unroll
        for (int j = 0; j < 18; ++j) h[j] = hr[j];
        #pragma unroll
        for (int p = 0; p < 16; ++p)
            acc[p] = fmaf(w0, h[p], fmaf(w1, h[p+1], fmaf(w2, h[p+2], acc[p])));
    }

    float ss = 0.f;
    float bb = bs[co];
    #pragma unroll
    for (int p = 0; p < 16; ++p) {
        int l = l0 + pbase + p;
        float hc = tile[co*(TL+2) + pbase + p + 1];
        float y = 0.5f*hc + 0.5f*(acc[p] + bb);
        int gi = (b*CC + co)*LL + l;
        float fh = g_fhat[gi] + y;
        if (outp) {
            outp[gi] = fh;                 // last scale: write output directly
        } else {
            g_fhat[gi] = fh;
            g_frest[gi] -= y;
        }
        float d = fh - f[gi];
        ss = fmaf(d, d, ss);
    }

    #pragma unroll
    for (int off = 16; off > 0; off >>= 1)
        ss += __shfl_xor_sync(0xffffffffu, ss, off);
    __shared__ float red[8];
    int lane = tid & 31, warp = tid >> 5;
    if (lane == 0) red[warp] = ss;
    __syncthreads();
    if (tid == 0) {
        float tot = 0.f;
        #pragma unroll
        for (int w = 0; w < 8; ++w) tot += red[w];
        atomicAdd(&g_loss, tot);
    }
}

// ---------------- tail: loss scalar (+ zero any padding) ----------------
__global__ void loss_kernel(float* __restrict__ out, int out_size) {
    int i = NELEM + blockIdx.x*256 + threadIdx.x;
    if (i >= out_size) return;
    out[i] = (i == NELEM) ? g_loss * (1.25f / (10.0f * (float)NELEM)) : 0.f;
}

// ---------------- launch ----------------
extern "C" void kernel_launch(void* const* d_in, const int* in_sizes, int n_in,
                              void* d_out, int out_size) {
    // Bind inputs BY ELEMENT COUNT (pairwise distinct -> ordering-immune)
    const float* f    = nullptr;
    const float* ew   = nullptr;
    const float* phiw = nullptr;
    const float* phib = nullptr;
    for (int i = 0; i < n_in; ++i) {
        switch (in_sizes[i]) {
            case 1048576: f    = (const float*)d_in[i]; break;
            case 524288:  ew   = (const float*)d_in[i]; break;
            case 49152:   phiw = (const float*)d_in[i]; break;
            case 256:     phib = (const float*)d_in[i]; break;
            default: break;
        }
    }
    float* out = (float*)d_out;

    const int seg[10] = {1,2,4,8,16,32,64,128,256,512};

    // pmap: bit-exact float64 replication of np.linspace + np.argmin(first-wins)
    int pmap[10];
    {
        double start = 1.0 / 12.0;
        double stop  = 1.0 - 1.0 / 12.0;
        double delta = stop - start;
        double step  = delta / 3.0;
        double ticks[4];
        for (int i = 0; i < 4; ++i) ticks[i] = (double)i * step + start;
        ticks[3] = stop;
        for (int si = 0; si < 10; ++si) {
            double x = (double)si / 9.0;
            int best = 0;
            double bd = fabs(ticks[0] - x);
            for (int i = 1; i < 4; ++i) {
                double d = fabs(ticks[i] - x);
                if (d < bd) { bd = d; best = i; }
            }
            pmap[si] = best;
        }
    }

    cudaFuncSetAttribute(phi_update_kernel,
                         cudaFuncAttributeMaxDynamicSharedMemorySize,
                         PHI_SMEM_FLOATS * (int)sizeof(float));

    normalize_cb_kernel<<<VV, 32>>>(ew);
    init_kernel<<<(NELEM + 255)/256, 256>>>(f);

    for (int si = 0; si < 10; ++si) {
        int s = seg[si];
        int ntok = BB * s;
        int r = LL / s;

        ds_norm_kernel<<<(ntok + 7)/8, 256>>>(s, r, ntok);

        int xblocks = (ntok + TOKB - 1)/TOKB;
        int vs = 1;
        while (xblocks * vs < 296 && vs < 64) vs <<= 1;   // pow2; chunk multiple of 128
        int chunk = VV / vs;
        dim3 agrid(xblocks, vs);
        argmax_kernel<<<agrid, 256>>>(ntok, chunk, vs);

        if (vs > 1)
            reduce_kernel<<<(ntok + 255)/256, 256>>>(ntok, vs);

        phi_update_kernel<<<BB*8, 256, PHI_SMEM_FLOATS*(int)sizeof(float)>>>(
            f, ew, phiw, phib, s, pmap[si], (si == 9) ? out : nullptr);
    }

    loss_kernel<<<(out_size - NELEM + 255)/256, 256>>>(out, out_size);
}

// round 11
// speedup vs baseline: 1.8129x; 1.1276x over previous
#include <cuda_runtime.h>
#include <math.h>

#define BB 32
#define CC 64
#define LL 512
#define VV 8192
#define NTOK_MAX (BB*LL)      /* 16384 */
#define NELEM (BB*CC*LL)      /* 1048576 */
#define TOKB 256              /* tokens per block, TPT1 kernel */
#define TR 128                /* codebook rows staged per tile */

// packed f32x2 helpers (sm_100+): lanewise IEEE fma on two packed floats
#define FMA_F32X2(d, a, b, c) \
    asm("fma.rn.f32x2 %0, %1, %2, %3;" : "=l"(d) : "l"(a), "l"(b), "l"(c))
#define UNPACK_F32X2(lo, hi, in) \
    asm("mov.b64 {%0, %1}, %2;" : "=r"(lo), "=r"(hi) : "l"(in))

// ---------------- device scratch (no malloc allowed) ----------------
__device__ float g_cbn[VV*CC];            // normalized codebook, 2MB
__device__ float g_frest[NELEM];          // residual, 4MB
__device__ float g_fhat[NELEM];           // reconstruction, 4MB
__device__ float g_rest_tok[NTOK_MAX*CC]; // downsampled+normalized tokens
__device__ int   g_idx[NTOK_MAX];         // selected codes
__device__ float g_pval[NTOK_MAX*64];     // per-vocab-split partial best val
__device__ int   g_pidx[NTOK_MAX*64];     // per-vocab-split partial best idx
__device__ float g_loss;                  // sum of squared err accum

// ---------------- codebook row-normalize (IEEE sqrt/div, fast-math-proof) ----
__global__ void normalize_cb_kernel(const float* __restrict__ ew) {
    int row = blockIdx.x;
    int lane = threadIdx.x;                 // 32 threads, 2 floats each
    float2 v = reinterpret_cast<const float2*>(ew + row*CC)[lane];
    float ss = v.x*v.x + v.y*v.y;
    #pragma unroll
    for (int off = 16; off > 0; off >>= 1)
        ss += __shfl_xor_sync(0xffffffffu, ss, off);
    float den = fmaxf(__fsqrt_rn(ss), 1e-12f);
    float2 o;
    o.x = __fdiv_rn(v.x, den);
    o.y = __fdiv_rn(v.y, den);
    reinterpret_cast<float2*>(g_cbn + row*CC)[lane] = o;
}

// ---------------- init residual / fhat / loss ----------------
__global__ void init_kernel(const float* __restrict__ f) {
    int i = blockIdx.x*256 + threadIdx.x;
    if (i < NELEM) { g_frest[i] = f[i]; g_fhat[i] = 0.f; }
    if (i == 0) g_loss = 0.f;
}

// ---------- fused area-downsample + row-normalize: warp per token ----------
__global__ void ds_norm_kernel(int s, int r, int ntok) {
    int t = blockIdx.x*8 + (threadIdx.x >> 5);
    if (t >= ntok) return;
    int lane = threadIdx.x & 31;
    int b = t / s, p = t - b*s;
    const float* s0 = g_frest + (b*CC + 2*lane)*LL + p*r;
    const float* s1 = s0 + LL;
    float va = 0.f, vb = 0.f;
    for (int j = 0; j < r; ++j) va += s0[j];
    for (int j = 0; j < r; ++j) vb += s1[j];
    float inv = 1.0f / (float)r;            // r power of two -> exact
    va *= inv; vb *= inv;
    float ss = va*va + vb*vb;
    #pragma unroll
    for (int off = 16; off > 0; off >>= 1)
        ss += __shfl_xor_sync(0xffffffffu, ss, off);
    float den = fmaxf(__fsqrt_rn(ss), 1e-12f);
    float2 o;
    o.x = __fdiv_rn(va, den);
    o.y = __fdiv_rn(vb, den);
    reinterpret_cast<float2*>(g_rest_tok)[t*32 + lane] = o;
}

// ------------- cosine argmax TPT1 (ntok<512): R10 validated kernel ---------
__global__ void __launch_bounds__(256) argmax_kernel(int ntok, int chunk, int vs) {
    __shared__ __align__(16) float4 s_cb[TR*16];   // 32KB tile

    int tid = threadIdx.x;
    int tg  = blockIdx.x * TOKB + tid;
    int tcl = (tg < ntok) ? tg : (ntok - 1);

    unsigned long long tok[32];
    {
        const ulonglong2* p =
            reinterpret_cast<const ulonglong2*>(g_rest_tok + tcl*CC);
        #pragma unroll
        for (int j = 0; j < 16; ++j) {
            ulonglong2 u = p[j];
            tok[2*j]   = u.x;
            tok[2*j+1] = u.y;
        }
    }

    float best = -1e30f; int bidx = 0;
    int vstart = blockIdx.y * chunk;
    int ntiles = chunk / TR;

    for (int tile = 0; tile < ntiles; ++tile) {
        __syncthreads();
        const float4* src = reinterpret_cast<const float4*>(g_cbn)
                          + (size_t)(vstart + tile*TR) * 16;
        #pragma unroll
        for (int k = 0; k < (TR*16)/256; ++k)
            s_cb[tid + k*256] = src[tid + k*256];
        __syncthreads();

        const ulonglong2* cb = reinterpret_cast<const ulonglong2*>(s_cb);
        int vbase = vstart + tile*TR;

        ulonglong2 cur[16], nxt[16];
        #pragma unroll
        for (int j = 0; j < 16; ++j) cur[j] = cb[j];

        #pragma unroll 1
        for (int row = 0; row < TR; row += 2) {
            #pragma unroll
            for (int j = 0; j < 16; ++j) nxt[j] = cb[(row+1)*16 + j];
            {
                unsigned long long a01 = 0ull, a23 = 0ull;
                #pragma unroll
                for (int j = 0; j < 16; ++j) {
                    FMA_F32X2(a01, cur[j].x, tok[2*j],   a01);
                    FMA_F32X2(a23, cur[j].y, tok[2*j+1], a23);
                }
                unsigned int uax, uay, uaz, uaw;
                UNPACK_F32X2(uax, uay, a01);
                UNPACK_F32X2(uaz, uaw, a23);
                float d = (__uint_as_float(uax) + __uint_as_float(uay))
                        + (__uint_as_float(uaz) + __uint_as_float(uaw));
                if (d > best) { best = d; bidx = vbase + row; }
            }
            if (row + 2 < TR) {
                #pragma unroll
                for (int j = 0; j < 16; ++j) cur[j] = cb[(row+2)*16 + j];
            }
            {
                unsigned long long a01 = 0ull, a23 = 0ull;
                #pragma unroll
                for (int j = 0; j < 16; ++j) {
                    FMA_F32X2(a01, nxt[j].x, tok[2*j],   a01);
                    FMA_F32X2(a23, nxt[j].y, tok[2*j+1], a23);
                }
                unsigned int uax, uay, uaz, uaw;
                UNPACK_F32X2(uax, uay, a01);
                UNPACK_F32X2(uaz, uaw, a23);
                float d = (__uint_as_float(uax) + __uint_as_float(uay))
                        + (__uint_as_float(uaz) + __uint_as_float(uaw));
                if (d > best) { best = d; bidx = vbase + row + 1; }
            }
        }
    }

    if (tg < ntok) {
        if (vs == 1) g_idx[tg] = bidx;
        else { g_pval[tg*64 + blockIdx.y] = best; g_pidx[tg*64 + blockIdx.y] = bidx; }
    }
}

// ------------- cosine argmax TPT2 (ntok>=512): 2 tokens/thread -------------
// 256 threads, tokens tg and tg+256 (ntok multiple of 512 -> no padding).
// Half-row double buffer (A,B of 8 ulonglong2): prefetch half h+1 while
// computing half h -> LDS latency hidden by 32 FFMA2 of compute per half.
// Per token: identical j=0..15 a01/a23 chains + (ax+ay)+(az+aw) horizontal.
__global__ void __launch_bounds__(256) argmax2_kernel(int ntok, int chunk, int vs) {
    __shared__ __align__(16) float4 s_cb[TR*16];   // 32KB tile

    int tid = threadIdx.x;
    int tgA = blockIdx.x * 512 + tid;
    int tgB = tgA + 256;
    int cA = (tgA < ntok) ? tgA : (ntok - 1);
    int cB = (tgB < ntok) ? tgB : (ntok - 1);

    unsigned long long ta[32], tb[32];
    {
        const ulonglong2* p =
            reinterpret_cast<const ulonglong2*>(g_rest_tok + cA*CC);
        const ulonglong2* q =
            reinterpret_cast<const ulonglong2*>(g_rest_tok + cB*CC);
        #pragma unroll
        for (int j = 0; j < 16; ++j) {
            ulonglong2 u = p[j]; ta[2*j] = u.x; ta[2*j+1] = u.y;
            ulonglong2 w = q[j]; tb[2*j] = w.x; tb[2*j+1] = w.y;
        }
    }

    float bestA = -1e30f, bestB = -1e30f; int idxA = 0, idxB = 0;
    int vstart = blockIdx.y * chunk;
    int ntiles = chunk / TR;

    for (int tile = 0; tile < ntiles; ++tile) {
        __syncthreads();
        const float4* src = reinterpret_cast<const float4*>(g_cbn)
                          + (size_t)(vstart + tile*TR) * 16;
        #pragma unroll
        for (int k = 0; k < (TR*16)/256; ++k)
            s_cb[tid + k*256] = src[tid + k*256];
        __syncthreads();

        const ulonglong2* cb = reinterpret_cast<const ulonglong2*>(s_cb);
        int vbase = vstart + tile*TR;

        ulonglong2 bufA[8], bufB[8];
        #pragma unroll
        for (int j = 0; j < 8; ++j) bufA[j] = cb[j];     // row0 half0

        #pragma unroll 1
        for (int row = 0; row < TR; ++row) {
            unsigned long long a01A = 0ull, a23A = 0ull;
            unsigned long long a01B = 0ull, a23B = 0ull;

            // prefetch half1 of this row
            #pragma unroll
            for (int j = 0; j < 8; ++j) bufB[j] = cb[row*16 + 8 + j];
            // compute half0 (j = 0..7)
            #pragma unroll
            for (int j = 0; j < 8; ++j) {
                FMA_F32X2(a01A, bufA[j].x, ta[2*j],   a01A);
                FMA_F32X2(a23A, bufA[j].y, ta[2*j+1], a23A);
                FMA_F32X2(a01B, bufA[j].x, tb[2*j],   a01B);
                FMA_F32X2(a23B, bufA[j].y, tb[2*j+1], a23B);
            }
            // prefetch half0 of next row
            if (row + 1 < TR) {
                #pragma unroll
                for (int j = 0; j < 8; ++j) bufA[j] = cb[(row+1)*16 + j];
            }
            // compute half1 (j = 8..15)
            #pragma unroll
            for (int j = 8; j < 16; ++j) {
                FMA_F32X2(a01A, bufB[j-8].x, ta[2*j],   a01A);
                FMA_F32X2(a23A, bufB[j-8].y, ta[2*j+1], a23A);
                FMA_F32X2(a01B, bufB[j-8].x, tb[2*j],   a01B);
                FMA_F32X2(a23B, bufB[j-8].y, tb[2*j+1], a23B);
            }

            unsigned int x0, x1, x2, x3;
            UNPACK_F32X2(x0, x1, a01A);
            UNPACK_F32X2(x2, x3, a23A);
            float dA = (__uint_as_float(x0) + __uint_as_float(x1))
                     + (__uint_as_float(x2) + __uint_as_float(x3));
            if (dA > bestA) { bestA = dA; idxA = vbase + row; }
            UNPACK_F32X2(x0, x1, a01B);
            UNPACK_F32X2(x2, x3, a23B);
            float dB = (__uint_as_float(x0) + __uint_as_float(x1))
                     + (__uint_as_float(x2) + __uint_as_float(x3));
            if (dB > bestB) { bestB = dB; idxB = vbase + row; }
        }
    }

    if (tgA < ntok) {
        if (vs == 1) g_idx[tgA] = idxA;
        else { g_pval[tgA*64 + blockIdx.y] = bestA; g_pidx[tgA*64 + blockIdx.y] = idxA; }
    }
    if (tgB < ntok) {
        if (vs == 1) g_idx[tgB] = idxB;
        else { g_pval[tgB*64 + blockIdx.y] = bestB; g_pidx[tgB*64 + blockIdx.y] = idxB; }
    }
}

// ---------------- reduce vocab splits per token (vs>1 only) ----------------
__global__ void reduce_kernel(int ntok, int vs) {
    int t = blockIdx.x*256 + threadIdx.x;
    if (t >= ntok) return;
    float bv = g_pval[t*64]; int bi = g_pidx[t*64];
    for (int sp = 1; sp < vs; ++sp) {
        float ov = g_pval[t*64 + sp]; int oi = g_pidx[t*64 + sp];
        if (ov > bv || (ov == bv && oi < bi)) { bv = ov; bi = oi; }
    }
    g_idx[t] = bi;
}

// ---------------- fused gather + upsample + Phi conv + residual update + loss ----------------
#define TL 64
#define PHI_SMEM_FLOATS (CC*(TL+2) + CC*193 + CC)
__global__ void __launch_bounds__(256) phi_update_kernel(
    const float* __restrict__ f, const float* __restrict__ ew,
    const float* __restrict__ phiw, const float* __restrict__ phib,
    int s, int pidx, float* __restrict__ outp)
{
    extern __shared__ float sm[];
    float* tile = sm;                 // [64][66]
    float* ws   = sm + CC*(TL+2);     // [64][193]
    float* bs   = ws + CC*193;        // [64]

    int b  = blockIdx.x >> 3;
    int l0 = (blockIdx.x & 7) * TL;
    int tid = threadIdx.x;

    const float* wsrc = phiw + pidx*CC*CC*3;
    for (int i = tid; i < CC*192; i += 256) {
        int co = i / 192, rem = i - co*192;
        ws[co*193 + rem] = wsrc[i];
    }
    if (tid < CC) bs[tid] = phib[pidx*CC + tid];

    for (int i = tid; i < CC*(TL+2); i += 256) {
        int ci = i / (TL+2), j = i - ci*(TL+2);
        int l = l0 + j - 1;
        float v = 0.f;
        if (l >= 0 && l < LL) {
            int tokp = (l * s) >> 9;
            int code = g_idx[b*s + tokp];
            v = ew[code*CC + ci];
        }
        tile[ci*(TL+2) + j] = v;
    }
    __syncthreads();

    int co = tid & 63;
    int pbase = (tid >> 6) * 16;
    float acc[16];
    #pragma unroll
    for (int p = 0; p < 16; ++p) acc[p] = 0.f;

    for (int ci = 0; ci < CC; ++ci) {
        const float* wr = ws + co*193 + ci*3;
        float w0 = wr[0], w1 = wr[1], w2 = wr[2];
        const float* hr = tile + ci*(TL+2) + pbase;
        float h[18];
        #pragma unroll
        for (int j = 0; j < 18; ++j) h[j] = hr[j];
        #pragma unroll
        for (int p = 0; p < 16; ++p)
            acc[p] = fmaf(w0, h[p], fmaf(w1, h[p+1], fmaf(w2, h[p+2], acc[p])));
    }

    float ss = 0.f;
    float bb = bs[co];
    #pragma unroll
    for (int p = 0; p < 16; ++p) {
        int l = l0 + pbase + p;
        float hc = tile[co*(TL+2) + pbase + p + 1];
        float y = 0.5f*hc + 0.5f*(acc[p] + bb);
        int gi = (b*CC + co)*LL + l;
        float fh = g_fhat[gi] + y;
        if (outp) {
            outp[gi] = fh;                 // last scale: write output directly
        } else {
            g_fhat[gi] = fh;
            g_frest[gi] -= y;
        }
        float d = fh - f[gi];
        ss = fmaf(d, d, ss);
    }

    #pragma unroll
    for (int off = 16; off > 0; off >>= 1)
        ss += __shfl_xor_sync(0xffffffffu, ss, off);
    __shared__ float red[8];
    int lane = tid & 31, warp = tid >> 5;
    if (lane == 0) red[warp] = ss;
    __syncthreads();
    if (tid == 0) {
        float tot = 0.f;
        #pragma unroll
        for (int w = 0; w < 8; ++w) tot += red[w];
        atomicAdd(&g_loss, tot);
    }
}

// ---------------- tail: loss scalar (+ zero any padding) ----------------
__global__ void loss_kernel(float* __restrict__ out, int out_size) {
    int i = NELEM + blockIdx.x*256 + threadIdx.x;
    if (i >= out_size) return;
    out[i] = (i == NELEM) ? g_loss * (1.25f / (10.0f * (float)NELEM)) : 0.f;
}

// ---------------- launch ----------------
extern "C" void kernel_launch(void* const* d_in, const int* in_sizes, int n_in,
                              void* d_out, int out_size) {
    // Bind inputs BY ELEMENT COUNT (pairwise distinct -> ordering-immune)
    const float* f    = nullptr;
    const float* ew   = nullptr;
    const float* phiw = nullptr;
    const float* phib = nullptr;
    for (int i = 0; i < n_in; ++i) {
        switch (in_sizes[i]) {
            case 1048576: f    = (const float*)d_in[i]; break;
            case 524288:  ew   = (const float*)d_in[i]; break;
            case 49152:   phiw = (const float*)d_in[i]; break;
            case 256:     phib = (const float*)d_in[i]; break;
            default: break;
        }
    }
    float* out = (float*)d_out;

    const int seg[10] = {1,2,4,8,16,32,64,128,256,512};

    // pmap: bit-exact float64 replication of np.linspace + np.argmin(first-wins)
    int pmap[10];
    {
        double start = 1.0 / 12.0;
        double stop  = 1.0 - 1.0 / 12.0;
        double delta = stop - start;
        double step  = delta / 3.0;
        double ticks[4];
        for (int i = 0; i < 4; ++i) ticks[i] = (double)i * step + start;
        ticks[3] = stop;
        for (int si = 0; si < 10; ++si) {
            double x = (double)si / 9.0;
            int best = 0;
            double bd = fabs(ticks[0] - x);
            for (int i = 1; i < 4; ++i) {
                double d = fabs(ticks[i] - x);
                if (d < bd) { bd = d; best = i; }
            }
            pmap[si] = best;
        }
    }

    cudaFuncSetAttribute(phi_update_kernel,
                         cudaFuncAttributeMaxDynamicSharedMemorySize,
                         PHI_SMEM_FLOATS * (int)sizeof(float));

    normalize_cb_kernel<<<VV, 32>>>(ew);
    init_kernel<<<(NELEM + 255)/256, 256>>>(f);

    for (int si = 0; si < 10; ++si) {
        int s = seg[si];
        int ntok = BB * s;
        int r = LL / s;

        ds_norm_kernel<<<(ntok + 7)/8, 256>>>(s, r, ntok);

        int vs;
        if (ntok >= 512) {
            int xblocks = ntok / 512;              // exact (ntok multiple of 512)
            vs = 1;
            while (xblocks * vs < 296 && vs < 64) vs <<= 1;
            int chunk = VV / vs;                   // multiple of TR=128
            dim3 agrid(xblocks, vs);
            argmax2_kernel<<<agrid, 256>>>(ntok, chunk, vs);
        } else {
            int xblocks = (ntok + TOKB - 1)/TOKB;
            vs = 1;
            while (xblocks * vs < 296 && vs < 64) vs <<= 1;
            int chunk = VV / vs;
            dim3 agrid(xblocks, vs);
            argmax_kernel<<<agrid, 256>>>(ntok, chunk, vs);
        }

        if (vs > 1)
            reduce_kernel<<<(ntok + 255)/256, 256>>>(ntok, vs);

        phi_update_kernel<<<BB*8, 256, PHI_SMEM_FLOATS*(int)sizeof(float)>>>(
            f, ew, phiw, phib, s, pmap[si], (si == 9) ? out : nullptr);
    }

    loss_kernel<<<(out_size - NELEM + 255)/256, 256>>>(out, out_size);
}